// round 8
// baseline (speedup 1.0000x reference)
#include <cuda_runtime.h>
#include <cuda_bf16.h>

#define NXv 432
#define NYv 496
#define CAPV (NXv * NYv)            // 214272 (NZ=1)
#define MAXP 100
#define NPTS_MAX 300000
#define NB_SCAN ((CAPV + 1023) / 1024)   // 210

// ---- scratch (static device globals; zero-initialized at module load).
// INVARIANT: g_count/g_count2 are all-zero on entry to kernel_launch and are
// re-zeroed by the tail blocks of k_out, keeping every call identical.
__device__ int g_count[CAPV];
__device__ int g_count2[CAPV];
__device__ int g_occPre[CAPV];     // per-lin scan partials (occupied flag)
__device__ int g_ptsPre[CAPV];     // per-lin scan partials (capped counts)
__device__ int g_base[CAPV];       // final point-slot base per lin
__device__ int g_lin[NPTS_MAX];
__device__ int g_tmpidx[NPTS_MAX];
__device__ int g_blkOcc[256];
__device__ int g_blkPts[256];
__device__ int g_tot[2];           // [0]=total occupied voxels, [1]=total capped pts
// compacted per-voxel metadata (indexed by compact voxel id)
__device__ int g_invlin[CAPV];
__device__ int g_ccount[CAPV];     // min(count, MAXP)
__device__ int g_fullcnt[CAPV];    // uncapped count
__device__ int g_cbase[CAPV];

// ---------------------------------------------------------------
// K1: per-point binning. NUMERICS LOCKED (R7 pass): XLA rewrites /const into
// *reciprocal(const); fp32(1/0.16f)=6.25f exactly, fp32(1/4.0f)=0.25f.
__global__ void k_bin(const float4* __restrict__ pts, int n) {
    int i = blockIdx.x * blockDim.x + threadIdx.x;
    if (i >= n) return;
    float4 p = pts[i];
    bool valid = (p.x >= 0.0f)    && (p.x < 69.12f) &&
                 (p.y >= -39.68f) && (p.y < 39.68f) &&
                 (p.z >= -3.0f)   && (p.z < 1.0f);
    int lin = CAPV;
    if (valid) {
        float qx = __fmul_rn(__fsub_rn(p.x,   0.0f),  6.25f);
        float qy = __fmul_rn(__fsub_rn(p.y, -39.68f), 6.25f);
        float qz = __fmul_rn(__fsub_rn(p.z,  -3.0f),  0.25f);
        int vx = (int)floorf(qx);
        int vy = (int)floorf(qy);
        int vz = (int)floorf(qz);
        vx = min(max(vx, 0), NXv - 1);
        vy = min(max(vy, 0), NYv - 1);
        vz = min(max(vz, 0), 0);
        lin = (vz * NYv + vy) * NXv + vx;
        atomicAdd(&g_count[lin], 1);
    }
    g_lin[i] = lin;
}

// K2: per-block scans via warp shuffles. 256 thr x 4 elem = 1024/block.
__global__ void k_scan1() {
    __shared__ int wO[8], wP[8];
    int b = blockIdx.x, t = threadIdx.x;
    int lane = t & 31, warp = t >> 5;
    int e0 = b * 1024 + t * 4;
    int occ[4], cap[4];
    int so = 0, sp = 0;
#pragma unroll
    for (int j = 0; j < 4; j++) {
        int e = e0 + j;
        int c = (e < CAPV) ? g_count[e] : 0;
        occ[j] = (c > 0) ? 1 : 0;
        cap[j] = (c < MAXP) ? c : MAXP;
        so += occ[j]; sp += cap[j];
    }
    int io = so, ip = sp;          // warp-inclusive scan
#pragma unroll
    for (int off = 1; off < 32; off <<= 1) {
        int vo = __shfl_up_sync(0xFFFFFFFFu, io, off);
        int vp = __shfl_up_sync(0xFFFFFFFFu, ip, off);
        if (lane >= off) { io += vo; ip += vp; }
    }
    if (lane == 31) { wO[warp] = io; wP[warp] = ip; }
    __syncthreads();
    if (warp == 0 && lane < 8) {
        int a = wO[lane], c2 = wP[lane];
#pragma unroll
        for (int off = 1; off < 8; off <<= 1) {
            int va = __shfl_up_sync(0xFFu, a,  off);
            int vc = __shfl_up_sync(0xFFu, c2, off);
            if (lane >= off) { a += va; c2 += vc; }
        }
        wO[lane] = a; wP[lane] = c2;
    }
    __syncthreads();
    int exO = (warp ? wO[warp - 1] : 0) + (io - so);
    int exP = (warp ? wP[warp - 1] : 0) + (ip - sp);
#pragma unroll
    for (int j = 0; j < 4; j++) {
        int e = e0 + j;
        if (e < CAPV) { g_occPre[e] = exO; g_ptsPre[e] = exP; }
        exO += occ[j]; exP += cap[j];
    }
    if (t == 255) { g_blkOcc[b] = wO[7]; g_blkPts[b] = wP[7]; }
}

// K3: exclusive scan of the 210 block totals; also publish grand totals.
__global__ void k_scan2() {
    __shared__ int sO[256], sP[256];
    int t = threadIdx.x;
    int vo = (t < NB_SCAN) ? g_blkOcc[t] : 0;
    int vp = (t < NB_SCAN) ? g_blkPts[t] : 0;
    sO[t] = vo; sP[t] = vp;
    __syncthreads();
    for (int off = 1; off < 256; off <<= 1) {
        int ao = 0, ap = 0;
        if (t >= off) { ao = sO[t - off]; ap = sP[t - off]; }
        __syncthreads();
        sO[t] += ao; sP[t] += ap;
        __syncthreads();
    }
    if (t == NB_SCAN - 1) { g_tot[0] = sO[t]; g_tot[1] = sP[t]; }
    if (t < NB_SCAN) { g_blkOcc[t] = sO[t] - vo; g_blkPts[t] = sP[t] - vp; }
}

// K4: finalize per-lin base; build compacted per-voxel metadata.
__global__ void k_final() {
    int e = blockIdx.x * blockDim.x + threadIdx.x;
    if (e >= CAPV) return;
    int b = e >> 10;
    int c = g_count[e];
    int bas = g_ptsPre[e] + g_blkPts[b];
    g_base[e] = bas;
    if (c > 0) {
        int vox = g_occPre[e] + g_blkOcc[b];
        g_invlin[vox]  = e;
        g_ccount[vox]  = (c < MAXP) ? c : MAXP;
        g_fullcnt[vox] = c;
        g_cbase[vox]   = bas;
    }
}

// K5: scatter point indices into compact per-voxel slots (arrival order).
__global__ void k_scatter(int n) {
    int i = blockIdx.x * blockDim.x + threadIdx.x;
    if (i >= n) return;
    int lin = g_lin[i];
    if (lin >= CAPV) return;
    int slot = atomicAdd(&g_count2[lin], 1);
    if (slot < MAXP) g_tmpidx[g_base[lin] + slot] = i;
}

// K6: per compact voxel, insertion-sort the slot indices back to original
// point order (reference's stable sort). lambda ~1.2 pts/voxel -> tiny sorts.
__global__ void k_sort() {
    int vox = blockIdx.x * blockDim.x + threadIdx.x;
    if (vox >= g_tot[0]) return;
    int cc = g_ccount[vox];
    if (cc <= 1) return;
    int bas = g_cbase[vox];
    for (int i = 1; i < cc; i++) {
        int key = g_tmpidx[bas + i];
        int j = i - 1;
        while (j >= 0 && g_tmpidx[bas + j] > key) {
            g_tmpidx[bas + j + 1] = g_tmpidx[bas + j];
            j--;
        }
        g_tmpidx[bas + j + 1] = key;
    }
}

// K7: single-writer output kernel — every output float4 written exactly once
// with its final value. Tail blocks re-zero the atomic counters for the next
// call (no k_out thread reads g_count/g_count2; readers use compact copies).
__global__ void k_out(const float4* __restrict__ pts, float4* __restrict__ out,
                      int n4, int voxF4, int coordE4, int voxFloats, int coordFloats) {
    int i = blockIdx.x * blockDim.x + threadIdx.x;
    if (i < n4) {
        int tot = g_tot[0];
        if (i < voxF4) {
            // voxel region: each row is exactly 100 float4s
            int vox  = i / MAXP;
            int slot = i - vox * MAXP;
            float4 v = make_float4(0.0f, 0.0f, 0.0f, 0.0f);
            if (vox < tot) {
                int cc = g_ccount[vox];
                if (slot < cc) v = pts[g_tmpidx[g_cbase[vox] + slot]];
            }
            out[i] = v;
        } else if (i < coordE4) {
            // coords region: 3 floats per row, handle 4 floats individually
            int f = i * 4 - voxFloats;
            float r[4];
#pragma unroll
            for (int k = 0; k < 4; k++) {
                int fc   = f + k;
                int row  = fc / 3;
                int comp = fc - row * 3;
                float val = -1.0f;
                if (row < tot) {
                    int lin = g_invlin[row];
                    int y = lin / NXv;       // z always 0 (NZ=1)
                    int x = lin - y * NXv;
                    val = (comp == 0) ? 0.0f : ((comp == 1) ? (float)y : (float)x);
                }
                r[k] = val;
            }
            out[i] = make_float4(r[0], r[1], r[2], r[3]);
        } else {
            // counts region: 1 float per row
            int f = i * 4 - voxFloats - coordFloats;
            float r[4];
#pragma unroll
            for (int k = 0; k < 4; k++) {
                int row = f + k;
                r[k] = (row < tot) ? (float)g_fullcnt[row] : 0.0f;
            }
            out[i] = make_float4(r[0], r[1], r[2], r[3]);
        }
    } else {
        // counter cleanup (int4 stores): restore the all-zero invariant
        int zi = i - n4;
        const int q = CAPV / 4;              // 53568
        if (zi < q)            ((int4*)g_count )[zi]     = make_int4(0, 0, 0, 0);
        else if (zi < 2 * q)   ((int4*)g_count2)[zi - q] = make_int4(0, 0, 0, 0);
    }
}

extern "C" void kernel_launch(void* const* d_in, const int* in_sizes, int n_in,
                              void* d_out, int out_size) {
    const float4* pts = (const float4*)d_in[0];
    int n = in_sizes[0] / 4;
    if (n > NPTS_MAX) n = NPTS_MAX;

    const long long voxFloats   = (long long)CAPV * MAXP * 4;  // 85,708,800
    const long long coordFloats = (long long)CAPV * 3;         // 642,816
    const long long total = (long long)out_size;

    const int n4      = (int)(total / 4);
    const int voxF4   = (int)(((total < voxFloats) ? total : voxFloats) / 4);
    long long cEnd    = voxFloats + coordFloats;
    const int coordE4 = (int)(((total < cEnd) ? total : cEnd) / 4);

    const int T = 256;
    const int zeroThreads = 2 * (CAPV / 4);            // 107,136
    const int outThreads  = n4 + zeroThreads;

    k_bin    <<<(n + T - 1) / T, T>>>(pts, n);
    k_scan1  <<<NB_SCAN, 256>>>();
    k_scan2  <<<1, 256>>>();
    k_final  <<<(CAPV + T - 1) / T, T>>>();
    k_scatter<<<(n + T - 1) / T, T>>>(n);
    k_sort   <<<(CAPV + T - 1) / T, T>>>();
    k_out    <<<(outThreads + T - 1) / T, T>>>(pts, (float4*)d_out, n4, voxF4,
                                               coordE4, (int)voxFloats, (int)coordFloats);
}

// round 9
// speedup vs baseline: 1.0026x; 1.0026x over previous
#include <cuda_runtime.h>
#include <cuda_bf16.h>

#define NXv 432
#define NYv 496
#define CAPV (NXv * NYv)            // 214272 (NZ=1)
#define MAXP 100
#define NPTS_MAX 300000
#define NB_SCAN ((CAPV + 1023) / 1024)   // 210

// ---- scratch (static device globals; zero-initialized at module load).
// INVARIANT: g_count/g_count2 are all-zero on entry to kernel_launch and are
// re-zeroed by the tail blocks of k_out, keeping every call identical.
__device__ int g_count[CAPV];
__device__ int g_count2[CAPV];
__device__ int g_occPre[CAPV];     // per-lin scan partials (occupied flag)
__device__ int g_ptsPre[CAPV];     // per-lin scan partials (capped counts)
__device__ int g_base[CAPV];       // final point-slot base per lin
__device__ int g_lin[NPTS_MAX];
__device__ int g_tmpidx[NPTS_MAX];
__device__ int g_blkOcc[256];
__device__ int g_blkPts[256];
__device__ int g_tot[2];           // [0]=total occupied voxels, [1]=total capped pts
// compacted per-voxel metadata (indexed by compact voxel id)
__device__ int g_invlin[CAPV];
__device__ int g_ccount[CAPV];     // min(count, MAXP)
__device__ int g_fullcnt[CAPV];    // uncapped count
__device__ int g_cbase[CAPV];

// ---------------------------------------------------------------
// K1: per-point binning. NUMERICS LOCKED (R7 pass): XLA rewrites /const into
// *reciprocal(const); fp32(1/0.16f)=6.25f exactly, fp32(1/4.0f)=0.25f.
__global__ void k_bin(const float4* __restrict__ pts, int n) {
    int i = blockIdx.x * blockDim.x + threadIdx.x;
    if (i >= n) return;
    float4 p = pts[i];
    bool valid = (p.x >= 0.0f)    && (p.x < 69.12f) &&
                 (p.y >= -39.68f) && (p.y < 39.68f) &&
                 (p.z >= -3.0f)   && (p.z < 1.0f);
    int lin = CAPV;
    if (valid) {
        float qx = __fmul_rn(__fsub_rn(p.x,   0.0f),  6.25f);
        float qy = __fmul_rn(__fsub_rn(p.y, -39.68f), 6.25f);
        float qz = __fmul_rn(__fsub_rn(p.z,  -3.0f),  0.25f);
        int vx = (int)floorf(qx);
        int vy = (int)floorf(qy);
        int vz = (int)floorf(qz);
        vx = min(max(vx, 0), NXv - 1);
        vy = min(max(vy, 0), NYv - 1);
        vz = min(max(vz, 0), 0);
        lin = (vz * NYv + vy) * NXv + vx;
        atomicAdd(&g_count[lin], 1);
    }
    g_lin[i] = lin;
}

// K2: per-block scans via warp shuffles. 256 thr x 4 elem = 1024/block.
__global__ void k_scan1() {
    __shared__ int wO[8], wP[8];
    int b = blockIdx.x, t = threadIdx.x;
    int lane = t & 31, warp = t >> 5;
    int e0 = b * 1024 + t * 4;
    int occ[4], cap[4];
    int so = 0, sp = 0;
#pragma unroll
    for (int j = 0; j < 4; j++) {
        int e = e0 + j;
        int c = (e < CAPV) ? g_count[e] : 0;
        occ[j] = (c > 0) ? 1 : 0;
        cap[j] = (c < MAXP) ? c : MAXP;
        so += occ[j]; sp += cap[j];
    }
    int io = so, ip = sp;          // warp-inclusive scan
#pragma unroll
    for (int off = 1; off < 32; off <<= 1) {
        int vo = __shfl_up_sync(0xFFFFFFFFu, io, off);
        int vp = __shfl_up_sync(0xFFFFFFFFu, ip, off);
        if (lane >= off) { io += vo; ip += vp; }
    }
    if (lane == 31) { wO[warp] = io; wP[warp] = ip; }
    __syncthreads();
    if (warp == 0 && lane < 8) {
        int a = wO[lane], c2 = wP[lane];
#pragma unroll
        for (int off = 1; off < 8; off <<= 1) {
            int va = __shfl_up_sync(0xFFu, a,  off);
            int vc = __shfl_up_sync(0xFFu, c2, off);
            if (lane >= off) { a += va; c2 += vc; }
        }
        wO[lane] = a; wP[lane] = c2;
    }
    __syncthreads();
    int exO = (warp ? wO[warp - 1] : 0) + (io - so);
    int exP = (warp ? wP[warp - 1] : 0) + (ip - sp);
#pragma unroll
    for (int j = 0; j < 4; j++) {
        int e = e0 + j;
        if (e < CAPV) { g_occPre[e] = exO; g_ptsPre[e] = exP; }
        exO += occ[j]; exP += cap[j];
    }
    if (t == 255) { g_blkOcc[b] = wO[7]; g_blkPts[b] = wP[7]; }
}

// K3: exclusive scan of the 210 block totals; also publish grand totals.
__global__ void k_scan2() {
    __shared__ int sO[256], sP[256];
    int t = threadIdx.x;
    int vo = (t < NB_SCAN) ? g_blkOcc[t] : 0;
    int vp = (t < NB_SCAN) ? g_blkPts[t] : 0;
    sO[t] = vo; sP[t] = vp;
    __syncthreads();
    for (int off = 1; off < 256; off <<= 1) {
        int ao = 0, ap = 0;
        if (t >= off) { ao = sO[t - off]; ap = sP[t - off]; }
        __syncthreads();
        sO[t] += ao; sP[t] += ap;
        __syncthreads();
    }
    if (t == NB_SCAN - 1) { g_tot[0] = sO[t]; g_tot[1] = sP[t]; }
    if (t < NB_SCAN) { g_blkOcc[t] = sO[t] - vo; g_blkPts[t] = sP[t] - vp; }
}

// K4: finalize per-lin base; build compacted per-voxel metadata.
__global__ void k_final() {
    int e = blockIdx.x * blockDim.x + threadIdx.x;
    if (e >= CAPV) return;
    int b = e >> 10;
    int c = g_count[e];
    int bas = g_ptsPre[e] + g_blkPts[b];
    g_base[e] = bas;
    if (c > 0) {
        int vox = g_occPre[e] + g_blkOcc[b];
        g_invlin[vox]  = e;
        g_ccount[vox]  = (c < MAXP) ? c : MAXP;
        g_fullcnt[vox] = c;
        g_cbase[vox]   = bas;
    }
}

// K5: scatter point indices into compact per-voxel slots (arrival order).
__global__ void k_scatter(int n) {
    int i = blockIdx.x * blockDim.x + threadIdx.x;
    if (i >= n) return;
    int lin = g_lin[i];
    if (lin >= CAPV) return;
    int slot = atomicAdd(&g_count2[lin], 1);
    if (slot < MAXP) g_tmpidx[g_base[lin] + slot] = i;
}

// K6: per compact voxel, insertion-sort the slot indices back to original
// point order (reference's stable sort). lambda ~1.2 pts/voxel -> tiny sorts.
__global__ void k_sort() {
    int vox = blockIdx.x * blockDim.x + threadIdx.x;
    if (vox >= g_tot[0]) return;
    int cc = g_ccount[vox];
    if (cc <= 1) return;
    int bas = g_cbase[vox];
    for (int i = 1; i < cc; i++) {
        int key = g_tmpidx[bas + i];
        int j = i - 1;
        while (j >= 0 && g_tmpidx[bas + j] > key) {
            g_tmpidx[bas + j + 1] = g_tmpidx[bas + j];
            j--;
        }
        g_tmpidx[bas + j + 1] = key;
    }
}

// K7: single-writer output kernel — every output float4 written exactly once
// with its final value. Tail blocks re-zero the atomic counters for the next
// call (no k_out thread reads g_count/g_count2; readers use compact copies).
__global__ void k_out(const float4* __restrict__ pts, float4* __restrict__ out,
                      int n4, int voxF4, int coordE4, int voxFloats, int coordFloats) {
    int i = blockIdx.x * blockDim.x + threadIdx.x;
    if (i < n4) {
        int tot = g_tot[0];
        if (i < voxF4) {
            // voxel region: each row is exactly 100 float4s
            int vox  = i / MAXP;
            int slot = i - vox * MAXP;
            float4 v = make_float4(0.0f, 0.0f, 0.0f, 0.0f);
            if (vox < tot) {
                int cc = g_ccount[vox];
                if (slot < cc) v = pts[g_tmpidx[g_cbase[vox] + slot]];
            }
            out[i] = v;
        } else if (i < coordE4) {
            // coords region: 3 floats per row, handle 4 floats individually
            int f = i * 4 - voxFloats;
            float r[4];
#pragma unroll
            for (int k = 0; k < 4; k++) {
                int fc   = f + k;
                int row  = fc / 3;
                int comp = fc - row * 3;
                float val = -1.0f;
                if (row < tot) {
                    int lin = g_invlin[row];
                    int y = lin / NXv;       // z always 0 (NZ=1)
                    int x = lin - y * NXv;
                    val = (comp == 0) ? 0.0f : ((comp == 1) ? (float)y : (float)x);
                }
                r[k] = val;
            }
            out[i] = make_float4(r[0], r[1], r[2], r[3]);
        } else {
            // counts region: 1 float per row
            int f = i * 4 - voxFloats - coordFloats;
            float r[4];
#pragma unroll
            for (int k = 0; k < 4; k++) {
                int row = f + k;
                r[k] = (row < tot) ? (float)g_fullcnt[row] : 0.0f;
            }
            out[i] = make_float4(r[0], r[1], r[2], r[3]);
        }
    } else {
        // counter cleanup (int4 stores): restore the all-zero invariant
        int zi = i - n4;
        const int q = CAPV / 4;              // 53568
        if (zi < q)            ((int4*)g_count )[zi]     = make_int4(0, 0, 0, 0);
        else if (zi < 2 * q)   ((int4*)g_count2)[zi - q] = make_int4(0, 0, 0, 0);
    }
}

extern "C" void kernel_launch(void* const* d_in, const int* in_sizes, int n_in,
                              void* d_out, int out_size) {
    const float4* pts = (const float4*)d_in[0];
    int n = in_sizes[0] / 4;
    if (n > NPTS_MAX) n = NPTS_MAX;

    const long long voxFloats   = (long long)CAPV * MAXP * 4;  // 85,708,800
    const long long coordFloats = (long long)CAPV * 3;         // 642,816
    const long long total = (long long)out_size;

    const int n4      = (int)(total / 4);
    const int voxF4   = (int)(((total < voxFloats) ? total : voxFloats) / 4);
    long long cEnd    = voxFloats + coordFloats;
    const int coordE4 = (int)(((total < cEnd) ? total : cEnd) / 4);

    const int T = 256;
    const int zeroThreads = 2 * (CAPV / 4);            // 107,136
    const int outThreads  = n4 + zeroThreads;

    k_bin    <<<(n + T - 1) / T, T>>>(pts, n);
    k_scan1  <<<NB_SCAN, 256>>>();
    k_scan2  <<<1, 256>>>();
    k_final  <<<(CAPV + T - 1) / T, T>>>();
    k_scatter<<<(n + T - 1) / T, T>>>(n);
    k_sort   <<<(CAPV + T - 1) / T, T>>>();
    k_out    <<<(outThreads + T - 1) / T, T>>>(pts, (float4*)d_out, n4, voxF4,
                                               coordE4, (int)voxFloats, (int)coordFloats);
}

// round 10
// speedup vs baseline: 1.3252x; 1.3218x over previous
#include <cuda_runtime.h>
#include <cuda_bf16.h>

#define NXv 432
#define NYv 496
#define CAPV (NXv * NYv)            // 214272 (NZ=1)
#define MAXP 100
#define NPTS_MAX 300000
#define NB 210                      // ceil(CAPV / 1024)

// ---- scratch (zero-initialized at load; k_post tail restores the invariant
// that g_count / g_count2 / g_look are all-zero on entry to every call) ----
__device__ int g_count[CAPV];
__device__ int g_count2[CAPV];
__device__ int g_base[CAPV];
__device__ int g_lin[NPTS_MAX];
__device__ int g_tmpidx[NPTS_MAX];
__device__ unsigned long long g_look[NB];   // decoupled-lookback words
__device__ int g_tot;                        // total occupied voxels
__device__ int4 g_cmeta[CAPV];               // per compact voxel: {lin, count, cbase, 0}

// Pack: bits[0:20)=pts prefix, bits[20:40)=occ prefix, bits[62:64)=status (1=AGG, 2=PREFIX)
__device__ __forceinline__ unsigned long long packLB(int st, int o, int p) {
    return ((unsigned long long)st << 62) |
           ((unsigned long long)(o & 0xFFFFF) << 20) |
           (unsigned long long)(p & 0xFFFFF);
}

// ---------------------------------------------------------------
// K_fill: pure streaming store — NO loads, NO metadata (R9 lesson).
__global__ void k_fill(float4* __restrict__ out, int n4, int cS4, int cE4) {
    int i = blockIdx.x * blockDim.x + threadIdx.x;
    if (i >= n4) return;
    float v = (i >= cS4 && i < cE4) ? -1.0f : 0.0f;
    out[i] = make_float4(v, v, v, v);
}

// K_bin: per-point binning. NUMERICS LOCKED (R7 pass): XLA rewrites /const
// into *reciprocal(const); fp32(1/0.16f)=6.25f exactly, fp32(1/4.0f)=0.25f.
__global__ void k_bin(const float4* __restrict__ pts, int n) {
    int i = blockIdx.x * blockDim.x + threadIdx.x;
    if (i >= n) return;
    float4 p = pts[i];
    bool valid = (p.x >= 0.0f)    && (p.x < 69.12f) &&
                 (p.y >= -39.68f) && (p.y < 39.68f) &&
                 (p.z >= -3.0f)   && (p.z < 1.0f);
    int lin = CAPV;
    if (valid) {
        float qx = __fmul_rn(__fsub_rn(p.x,   0.0f),  6.25f);
        float qy = __fmul_rn(__fsub_rn(p.y, -39.68f), 6.25f);
        int vx = min(max((int)floorf(qx), 0), NXv - 1);
        int vy = min(max((int)floorf(qy), 0), NYv - 1);
        lin = vy * NXv + vx;     // vz always 0 (NZ=1; z-range already validated)
        atomicAdd(&g_count[lin], 1);
    }
    g_lin[i] = lin;
}

// K_scan: single-pass decoupled-lookback scan over (occupied, cappedCount).
// 210 blocks x 256 threads x 4 elements. Emits g_base per lin and compact
// per-voxel metadata, plus the grand total.
__global__ void k_scan() {
    __shared__ int wO[8], wP[8];
    __shared__ int sExc[2];
    int b = blockIdx.x, t = threadIdx.x;
    int lane = t & 31, warp = t >> 5;
    int e0 = b * 1024 + t * 4;
    int occ[4], cap[4], cnt[4];
    int so = 0, sp = 0;
#pragma unroll
    for (int j = 0; j < 4; j++) {
        int e = e0 + j;
        int c = (e < CAPV) ? g_count[e] : 0;
        cnt[j] = c;
        occ[j] = (c > 0) ? 1 : 0;
        cap[j] = (c < MAXP) ? c : MAXP;
        so += occ[j]; sp += cap[j];
    }
    int io = so, ip = sp;            // warp-inclusive scan
#pragma unroll
    for (int off = 1; off < 32; off <<= 1) {
        int vo = __shfl_up_sync(0xFFFFFFFFu, io, off);
        int vp = __shfl_up_sync(0xFFFFFFFFu, ip, off);
        if (lane >= off) { io += vo; ip += vp; }
    }
    if (lane == 31) { wO[warp] = io; wP[warp] = ip; }
    __syncthreads();
    if (warp == 0 && lane < 8) {
        int a = wO[lane], c2 = wP[lane];
#pragma unroll
        for (int off = 1; off < 8; off <<= 1) {
            int va = __shfl_up_sync(0xFFu, a,  off);
            int vc = __shfl_up_sync(0xFFu, c2, off);
            if (lane >= off) { a += va; c2 += vc; }
        }
        wO[lane] = a; wP[lane] = c2;
    }
    __syncthreads();
    int blkO = wO[7], blkP = wP[7];

    // ---- decoupled lookback (warp 0) ----
    if (t < 32) {
        if (lane == 0 && b > 0) {
            // publish AGG early so successors can progress
            *(volatile unsigned long long*)(g_look + b) = packLB(1, blkO, blkP);
        }
        int accO = 0, accP = 0;
        if (b > 0) {
            int end = b;
            for (;;) {
                int idx = end - 1 - lane;
                unsigned long long v = 0;
                if (idx >= 0) {
                    volatile unsigned long long* vp = g_look + idx;
                    do { v = *vp; } while ((v >> 62) == 0ull);
                }
                bool isPref = (idx >= 0) && ((v >> 62) == 2ull);
                unsigned pm = __ballot_sync(0xFFFFFFFFu, isPref);
                int o  = (idx >= 0) ? (int)((v >> 20) & 0xFFFFF) : 0;
                int p2 = (idx >= 0) ? (int)(v & 0xFFFFF) : 0;
                if (pm) {
                    int fp = __ffs(pm) - 1;   // nearest PREFIX lane
                    if (lane > fp) { o = 0; p2 = 0; }
#pragma unroll
                    for (int off = 16; off; off >>= 1) {
                        o  += __shfl_down_sync(0xFFFFFFFFu, o,  off);
                        p2 += __shfl_down_sync(0xFFFFFFFFu, p2, off);
                    }
                    if (lane == 0) { accO += o; accP += p2; }
                    break;
                } else {
#pragma unroll
                    for (int off = 16; off; off >>= 1) {
                        o  += __shfl_down_sync(0xFFFFFFFFu, o,  off);
                        p2 += __shfl_down_sync(0xFFFFFFFFu, p2, off);
                    }
                    if (lane == 0) { accO += o; accP += p2; }
                    end -= 32;
                }
            }
        }
        if (lane == 0) {
            sExc[0] = accO; sExc[1] = accP;
            *(volatile unsigned long long*)(g_look + b) =
                packLB(2, accO + blkO, accP + blkP);
            if (b == NB - 1) g_tot = accO + blkO;
        }
    }
    __syncthreads();

    int exO = sExc[0] + (warp ? wO[warp - 1] : 0) + (io - so);
    int exP = sExc[1] + (warp ? wP[warp - 1] : 0) + (ip - sp);
#pragma unroll
    for (int j = 0; j < 4; j++) {
        int e = e0 + j;
        if (e < CAPV) {
            g_base[e] = exP;
            if (cnt[j] > 0) g_cmeta[exO] = make_int4(e, cnt[j], exP, 0);
        }
        exO += occ[j]; exP += cap[j];
    }
}

// K_scatter: point indices into compact per-voxel slots (arrival order).
__global__ void k_scatter(int n) {
    int i = blockIdx.x * blockDim.x + threadIdx.x;
    if (i >= n) return;
    int lin = g_lin[i];
    if (lin >= CAPV) return;
    int slot = atomicAdd(&g_count2[lin], 1);
    if (slot < MAXP) g_tmpidx[g_base[lin] + slot] = i;
}

// K_post: per compact voxel — insertion-sort slots back to original point
// order (the stable sort), write feature rows + coords + counts. Tail blocks
// restore the all-zero scratch invariant for the next call.
__global__ void k_post(const float4* __restrict__ pts, float* __restrict__ out,
                       int hasCoords, int hasCounts) {
    const long long voxFloats   = (long long)CAPV * MAXP * 4;
    const long long coordFloats = (long long)CAPV * 3;
    int i = blockIdx.x * blockDim.x + threadIdx.x;
    if (i < CAPV) {
        if (i >= g_tot) return;
        int4 m = g_cmeta[i];
        int lin = m.x, c = m.y, bas = m.z;
        int cc = (c < MAXP) ? c : MAXP;
        for (int a = 1; a < cc; a++) {
            int key = g_tmpidx[bas + a];
            int j = a - 1;
            while (j >= 0 && g_tmpidx[bas + j] > key) {
                g_tmpidx[bas + j + 1] = g_tmpidx[bas + j];
                j--;
            }
            g_tmpidx[bas + j + 1] = key;
        }
        float4* row = (float4*)out + (size_t)i * MAXP;
        for (int j = 0; j < cc; j++) row[j] = pts[g_tmpidx[bas + j]];
        if (hasCoords) {
            int y = lin / NXv, x = lin - y * NXv;
            float* cr = out + voxFloats + (size_t)i * 3;
            cr[0] = 0.0f; cr[1] = (float)y; cr[2] = (float)x;
        }
        if (hasCounts) out[voxFloats + coordFloats + i] = (float)c;
    } else {
        int zi = i - CAPV;
        const int q = CAPV / 4;               // 53568
        if (zi < q)            ((int4*)g_count )[zi]     = make_int4(0, 0, 0, 0);
        else if (zi < 2 * q)   ((int4*)g_count2)[zi - q] = make_int4(0, 0, 0, 0);
        else if (zi < 2 * q + NB) g_look[zi - 2 * q] = 0ull;
    }
}

extern "C" void kernel_launch(void* const* d_in, const int* in_sizes, int n_in,
                              void* d_out, int out_size) {
    const float4* pts = (const float4*)d_in[0];
    int n = in_sizes[0] / 4;
    if (n > NPTS_MAX) n = NPTS_MAX;

    const long long voxFloats   = (long long)CAPV * MAXP * 4;  // 85,708,800
    const long long coordFloats = (long long)CAPV * 3;         // 642,816
    const long long total = (long long)out_size;

    const int hasCoords = (total >= voxFloats + coordFloats) ? 1 : 0;
    const int hasCounts = (total >= voxFloats + coordFloats + CAPV) ? 1 : 0;
    const int n4  = (int)(total / 4);
    const int cS4 = hasCoords ? (int)(voxFloats / 4) : n4;
    const int cE4 = hasCoords ? (int)((voxFloats + coordFloats) / 4) : n4;

    const int T = 256;
    const int postThreads = CAPV + 2 * (CAPV / 4) + NB;

    k_fill   <<<(n4 + T - 1) / T, T>>>((float4*)d_out, n4, cS4, cE4);
    k_bin    <<<(n + T - 1) / T, T>>>(pts, n);
    k_scan   <<<NB, 256>>>();
    k_scatter<<<(n + T - 1) / T, T>>>(n);
    k_post   <<<(postThreads + T - 1) / T, T>>>(pts, (float*)d_out, hasCoords, hasCounts);
}

// round 11
// speedup vs baseline: 1.3515x; 1.0198x over previous
#include <cuda_runtime.h>
#include <cuda_bf16.h>

#define NXv 432
#define NYv 496
#define CAPV (NXv * NYv)            // 214272 (NZ=1)
#define MAXP 100
#define NPTS_MAX 300000
#define NB 210                      // ceil(CAPV / 1024)

// ---- scratch (zero-initialized at load; k_post tail restores the invariant
// that g_count / g_look are all-zero on entry to every call). g_slots needs
// no cleaning: reads are always bounded by the current call's count. ----
__device__ int g_count[CAPV];
__device__ int g_slots[CAPV * MAXP];         // per-voxel point-index slots (85.7 MB)
__device__ unsigned long long g_look[NB];    // decoupled-lookback words
__device__ int g_tot;                        // total occupied voxels
__device__ int2 g_cmeta[CAPV];               // per compact voxel: {lin, count}

// Pack: bits[0:20)=pts prefix (unused now, kept), bits[20:40)=occ prefix,
// bits[62:64)=status (1=AGG, 2=PREFIX)
__device__ __forceinline__ unsigned long long packLB(int st, int o, int p) {
    return ((unsigned long long)st << 62) |
           ((unsigned long long)(o & 0xFFFFF) << 20) |
           (unsigned long long)(p & 0xFFFFF);
}

// ---------------------------------------------------------------
// K_fill: pure streaming store — NO loads, NO metadata (R9 lesson).
__global__ void k_fill(float4* __restrict__ out, int n4, int cS4, int cE4) {
    int i = blockIdx.x * blockDim.x + threadIdx.x;
    if (i >= n4) return;
    float v = (i >= cS4 && i < cE4) ? -1.0f : 0.0f;
    out[i] = make_float4(v, v, v, v);
}

// K_bin: per-point binning WITH fused slot scatter. The arrival slot comes
// free from the counting atomicAdd (this is what the old k_scatter recomputed
// with a second atomic pass). NUMERICS LOCKED (R7): XLA rewrites /const into
// *reciprocal(const); fp32(1/0.16f)=6.25f exactly.
__global__ void k_bin(const float4* __restrict__ pts, int n) {
    int i = blockIdx.x * blockDim.x + threadIdx.x;
    if (i >= n) return;
    float4 p = pts[i];
    bool valid = (p.x >= 0.0f)    && (p.x < 69.12f) &&
                 (p.y >= -39.68f) && (p.y < 39.68f) &&
                 (p.z >= -3.0f)   && (p.z < 1.0f);
    if (!valid) return;
    float qx = __fmul_rn(__fsub_rn(p.x,   0.0f),  6.25f);
    float qy = __fmul_rn(__fsub_rn(p.y, -39.68f), 6.25f);
    int vx = min(max((int)floorf(qx), 0), NXv - 1);
    int vy = min(max((int)floorf(qy), 0), NYv - 1);
    int lin = vy * NXv + vx;          // vz always 0 (NZ=1; z-range validated)
    int slot = atomicAdd(&g_count[lin], 1);
    if (slot < MAXP) g_slots[lin * MAXP + slot] = i;
}

// K_scan: single-pass decoupled-lookback scan over the occupied flag.
// 210 blocks x 256 threads x 4 elements. Emits compact per-voxel metadata
// {lin, count} in ascending-lin order, plus the grand total.
__global__ void k_scan() {
    __shared__ int wO[8];
    __shared__ int sExc;
    int b = blockIdx.x, t = threadIdx.x;
    int lane = t & 31, warp = t >> 5;
    int e0 = b * 1024 + t * 4;
    int occ[4], cnt[4];
    int so = 0;
#pragma unroll
    for (int j = 0; j < 4; j++) {
        int e = e0 + j;
        int c = (e < CAPV) ? g_count[e] : 0;
        cnt[j] = c;
        occ[j] = (c > 0) ? 1 : 0;
        so += occ[j];
    }
    int io = so;                      // warp-inclusive scan
#pragma unroll
    for (int off = 1; off < 32; off <<= 1) {
        int vo = __shfl_up_sync(0xFFFFFFFFu, io, off);
        if (lane >= off) io += vo;
    }
    if (lane == 31) wO[warp] = io;
    __syncthreads();
    if (warp == 0 && lane < 8) {
        int a = wO[lane];
#pragma unroll
        for (int off = 1; off < 8; off <<= 1) {
            int va = __shfl_up_sync(0xFFu, a, off);
            if (lane >= off) a += va;
        }
        wO[lane] = a;
    }
    __syncthreads();
    int blkO = wO[7];

    // ---- decoupled lookback (warp 0) ----
    if (t < 32) {
        if (lane == 0 && b > 0) {
            *(volatile unsigned long long*)(g_look + b) = packLB(1, blkO, 0);
        }
        int accO = 0;
        if (b > 0) {
            int end = b;
            for (;;) {
                int idx = end - 1 - lane;
                unsigned long long v = 0;
                if (idx >= 0) {
                    volatile unsigned long long* vp = g_look + idx;
                    do { v = *vp; } while ((v >> 62) == 0ull);
                }
                bool isPref = (idx >= 0) && ((v >> 62) == 2ull);
                unsigned pm = __ballot_sync(0xFFFFFFFFu, isPref);
                int o = (idx >= 0) ? (int)((v >> 20) & 0xFFFFF) : 0;
                if (pm) {
                    int fp = __ffs(pm) - 1;
                    if (lane > fp) o = 0;
#pragma unroll
                    for (int off = 16; off; off >>= 1)
                        o += __shfl_down_sync(0xFFFFFFFFu, o, off);
                    if (lane == 0) accO += o;
                    break;
                } else {
#pragma unroll
                    for (int off = 16; off; off >>= 1)
                        o += __shfl_down_sync(0xFFFFFFFFu, o, off);
                    if (lane == 0) accO += o;
                    end -= 32;
                }
            }
        }
        if (lane == 0) {
            sExc = accO;
            *(volatile unsigned long long*)(g_look + b) = packLB(2, accO + blkO, 0);
            if (b == NB - 1) g_tot = accO + blkO;
        }
    }
    __syncthreads();

    int exO = sExc + (warp ? wO[warp - 1] : 0) + (io - so);
#pragma unroll
    for (int j = 0; j < 4; j++) {
        int e = e0 + j;
        if (e < CAPV && cnt[j] > 0) g_cmeta[exO] = make_int2(e, cnt[j]);
        exO += occ[j];
    }
}

// K_post: per compact voxel — copy slots, insertion-sort back to original
// point order (the reference's stable sort), gather features, write rows +
// coords + counts. Tail blocks restore the all-zero scratch invariant.
__global__ void k_post(const float4* __restrict__ pts, float* __restrict__ out,
                       int hasCoords, int hasCounts) {
    const long long voxFloats   = (long long)CAPV * MAXP * 4;
    const long long coordFloats = (long long)CAPV * 3;
    int i = blockIdx.x * blockDim.x + threadIdx.x;
    if (i < CAPV) {
        if (i >= g_tot) return;
        int2 m = g_cmeta[i];
        int lin = m.x, c = m.y;
        int cc = (c < MAXP) ? c : MAXP;
        const int* srow = g_slots + (size_t)lin * MAXP;
        int a[MAXP];
        for (int j = 0; j < cc; j++) a[j] = srow[j];
        for (int s = 1; s < cc; s++) {          // tiny sorts: mean ~1.7/voxel
            int key = a[s];
            int j = s - 1;
            while (j >= 0 && a[j] > key) { a[j + 1] = a[j]; j--; }
            a[j + 1] = key;
        }
        float4* row = (float4*)out + (size_t)i * MAXP;
        for (int j = 0; j < cc; j++) row[j] = pts[a[j]];
        if (hasCoords) {
            int y = lin / NXv, x = lin - y * NXv;
            float* cr = out + voxFloats + (size_t)i * 3;
            cr[0] = 0.0f; cr[1] = (float)y; cr[2] = (float)x;
        }
        if (hasCounts) out[voxFloats + coordFloats + i] = (float)c;
    } else {
        int zi = i - CAPV;
        const int q = CAPV / 4;                 // 53568
        if (zi < q)           ((int4*)g_count)[zi] = make_int4(0, 0, 0, 0);
        else if (zi < q + NB) g_look[zi - q] = 0ull;
    }
}

extern "C" void kernel_launch(void* const* d_in, const int* in_sizes, int n_in,
                              void* d_out, int out_size) {
    const float4* pts = (const float4*)d_in[0];
    int n = in_sizes[0] / 4;
    if (n > NPTS_MAX) n = NPTS_MAX;

    const long long voxFloats   = (long long)CAPV * MAXP * 4;  // 85,708,800
    const long long coordFloats = (long long)CAPV * 3;         // 642,816
    const long long total = (long long)out_size;

    const int hasCoords = (total >= voxFloats + coordFloats) ? 1 : 0;
    const int hasCounts = (total >= voxFloats + coordFloats + CAPV) ? 1 : 0;
    const int n4  = (int)(total / 4);
    const int cS4 = hasCoords ? (int)(voxFloats / 4) : n4;
    const int cE4 = hasCoords ? (int)((voxFloats + coordFloats) / 4) : n4;

    const int T = 256;
    const int postThreads = CAPV + (CAPV / 4) + NB;

    // Side stream + fork/join events, created once on the first (correctness)
    // call — never during graph capture. Non-blocking to avoid legacy-stream
    // implicit synchronization.
    static cudaStream_t s_side = nullptr;
    static cudaEvent_t  e_fork = nullptr, e_join = nullptr;
    if (s_side == nullptr) {
        cudaStreamCreateWithFlags(&s_side, cudaStreamNonBlocking);
        cudaEventCreateWithFlags(&e_fork, cudaEventDisableTiming);
        cudaEventCreateWithFlags(&e_join, cudaEventDisableTiming);
    }

    // Fork: bin -> scan on the side stream, concurrent with the big fill.
    cudaEventRecord(e_fork, 0);
    cudaStreamWaitEvent(s_side, e_fork, 0);
    k_bin <<<(n + T - 1) / T, T, 0, s_side>>>(pts, n);
    k_scan<<<NB, 256, 0, s_side>>>();
    cudaEventRecord(e_join, s_side);

    k_fill<<<(n4 + T - 1) / T, T>>>((float4*)d_out, n4, cS4, cE4);

    // Join: post needs both the fill (it overwrites rows) and the scan.
    cudaStreamWaitEvent(0, e_join, 0);
    k_post<<<(postThreads + T - 1) / T, T>>>(pts, (float*)d_out, hasCoords, hasCounts);
}